// round 3
// baseline (speedup 1.0000x reference)
#include <cuda_runtime.h>
#include <cstdint>

// S3FD anchor assignment with spatial binning.
//   k_cells:   per-anchor cell id (16x16 grid of 64px cells by center) + histogram
//   k_scan:    prefix-sum cells -> bin offsets, build chunk worklist (1024 anchors/chunk)
//   k_gtlist:  per-cell list of GTs intersecting the cell expanded by 65px
//              (64 = max anchor half-extent, +1 slack for center rounding)
//   k_main:    per-chunk: IoU of its anchors vs the cell's GT list only.
//              max/argmax -> stage-1 assign; per-GT top-3 via lock-free atomicMax
//              cascade (smem per block, merged to global).
//   k2:        per-GT claims -> atomicMax scatter into forced[]
//   k3:        assign = forced >= 0 ? forced : assign
// Output dtype is float32; values are small ints stored as floats.
// IoU arithmetic uses explicit __f*_rn intrinsics: bit-identical to the f32 reference.

#define TPB 256
#define APT 4
#define CHUNK (TPB * APT)      // 1024 anchors per work chunk
#define MAXM 256               // >= n_gt (200)
#define MAXN (1 << 20)         // >= n_anchor (500000)
#define NCELL 256
#define GRIDW 16
#define CELL_PX 64.0f
#define EXPAND 65.0f           // 64 max anchor half-extent + 1px rounding slack

__device__ int g_hist[NCELL];
__device__ int g_offs[NCELL];
__device__ int g_cursor[NCELL];
__device__ int g_nwork;
__device__ int4 g_work[NCELL + MAXN / CHUNK + 2];   // (cell, start, len, 0)
__device__ unsigned short g_cellid[MAXN];
__device__ int g_binned[MAXN];                      // binned -> original anchor idx
__device__ float4 g_bbox[MAXN];                     // binned anchor boxes (coalesced reads)
__device__ int g_gtcnt[NCELL];
__device__ int g_gtlist[NCELL * MAXM];
__device__ unsigned long long g_top3[MAXM * 3];
__device__ int g_forced[MAXN];

// Lock-free top-3 insert: slots monotone non-decreasing under atomicMax; the
// displaced minimum cascades down. Keys are distinct (low bits = ~anchor idx),
// so the final state is the exact sorted top-3 of all inserted keys.
__device__ __forceinline__ void cascade_insert(unsigned long long* s, unsigned long long v) {
#pragma unroll
    for (int i = 0; i < 3; i++) {
        unsigned long long old = atomicMax(&s[i], v);
        v = old < v ? old : v;
        if (v == 0ull) return;
    }
}

__global__ void k_cells(const float4* __restrict__ anc, int n) {
    int i = blockIdx.x * blockDim.x + threadIdx.x;
    if (i >= n) return;
    float4 a = anc[i];
    int cx = min(GRIDW - 1, max(0, (int)((a.x + a.z) * (0.5f / CELL_PX))));
    int cy = min(GRIDW - 1, max(0, (int)((a.y + a.w) * (0.5f / CELL_PX))));
    int c = cy * GRIDW + cx;
    g_cellid[i] = (unsigned short)c;
    atomicAdd(&g_hist[c], 1);
}

__global__ void k_scan(int n) {
    __shared__ int s[NCELL];
    int t = threadIdx.x;                    // 256 threads == NCELL
    int v = g_hist[t];
    s[t] = v; __syncthreads();
    for (int d = 1; d < NCELL; d <<= 1) {   // inclusive Hillis-Steele
        int x = (t >= d) ? s[t - d] : 0; __syncthreads();
        s[t] += x; __syncthreads();
    }
    int excl = s[t] - v;
    g_offs[t] = excl;
    g_cursor[t] = excl;
    int ch = (v + CHUNK - 1) / CHUNK;
    __syncthreads();
    s[t] = ch; __syncthreads();
    for (int d = 1; d < NCELL; d <<= 1) {
        int x = (t >= d) ? s[t - d] : 0; __syncthreads();
        s[t] += x; __syncthreads();
    }
    int chexcl = s[t] - ch;
    if (t == NCELL - 1) g_nwork = s[t];
    for (int k = 0; k < ch; k++) {
        int start = excl + k * CHUNK;
        int len = min(CHUNK, v - k * CHUNK);
        g_work[chexcl + k] = make_int4(t, start, len, 0);
    }
}

__global__ void k_gtlist(const float4* __restrict__ gts, int m) {
    int c = threadIdx.x;                    // 256 threads == NCELL
    float cx0 = (c & (GRIDW - 1)) * CELL_PX - EXPAND;
    float cx1 = (c & (GRIDW - 1)) * CELL_PX + CELL_PX + EXPAND;
    float cy0 = (c >> 4) * CELL_PX - EXPAND;
    float cy1 = (c >> 4) * CELL_PX + CELL_PX + EXPAND;
    int cnt = 0;
    for (int g = 0; g < m; g++) {
        float4 G = gts[g];
        if (G.x <= cx1 && G.z >= cx0 && G.y <= cy1 && G.w >= cy0)
            g_gtlist[c * MAXM + cnt++] = g;
    }
    g_gtcnt[c] = cnt;
}

__global__ void k_scatter(const float4* __restrict__ anc, int n) {
    int i = blockIdx.x * blockDim.x + threadIdx.x;
    if (i >= n) return;
    int c = g_cellid[i];
    int pos = atomicAdd(&g_cursor[c], 1);
    g_binned[pos] = i;
    g_bbox[pos] = anc[i];
}

__global__ void __launch_bounds__(TPB) k_main(
    const float4* __restrict__ gts, float* __restrict__ out,
    unsigned long long* __restrict__ gtop)
{
    __shared__ float4 sgc[MAXM];                 // compacted GT boxes for this cell
    __shared__ float sga[MAXM];                  // GT areas
    __shared__ int sgi[MAXM];                    // compact -> original GT idx
    __shared__ unsigned long long stop[MAXM * 3];

    if (blockIdx.x >= g_nwork) return;
    int4 w = g_work[blockIdx.x];
    const int cell = w.x, astart = w.y, alen = w.z;
    const int tid = threadIdx.x;

    const int cnt = g_gtcnt[cell];
    if (tid < cnt) {
        int gi = g_gtlist[cell * MAXM + tid];
        float4 G = gts[gi];
        sgc[tid] = G;
        sga[tid] = __fmul_rn(__fsub_rn(G.z, G.x), __fsub_rn(G.w, G.y));
        sgi[tid] = gi;
    }
    for (int i = tid; i < MAXM * 3; i += TPB) stop[i] = 0ull;
    __syncthreads();

    float ax1[APT], ay1[APT], ax2[APT], ay2[APT], aar[APT], best[APT];
    int bc[APT], aidx[APT];
    bool act[APT];
#pragma unroll
    for (int j = 0; j < APT; j++) {
        int p = tid + j * TPB;
        act[j] = p < alen;
        float4 a = act[j] ? g_bbox[astart + p] : make_float4(0.f, 0.f, 0.f, 0.f);
        aidx[j] = act[j] ? g_binned[astart + p] : 0;
        ax1[j] = a.x; ay1[j] = a.y; ax2[j] = a.z; ay2[j] = a.w;
        aar[j] = __fmul_rn(__fsub_rn(a.z, a.x), __fsub_rn(a.w, a.y));
        best[j] = 0.f;   // all-zero row -> ref argmax 0; bidx only used when best>0.5
        bc[j] = 0;
    }

    // Stale-read skip gate: high 32 bits of slot 2 are monotone non-decreasing,
    // so a racy 32-bit read is always a safe lower bound.
    const unsigned* stop_hi = (const unsigned*)stop;

    for (int c = 0; c < cnt; c++) {
        float4 G = sgc[c];
        float ga = sga[c];
        unsigned min_hi = stop_hi[(c * 3 + 2) * 2 + 1];
#pragma unroll
        for (int j = 0; j < APT; j++) {
            float ltx = fmaxf(ax1[j], G.x), lty = fmaxf(ay1[j], G.y);
            float rbx = fminf(ax2[j], G.z), rby = fminf(ay2[j], G.w);
            float wd = fmaxf(__fsub_rn(rbx, ltx), 0.f);
            float ht = fmaxf(__fsub_rn(rby, lty), 0.f);
            float inter = __fmul_rn(wd, ht);
            if (inter > 0.f && act[j]) {
                float denom = __fsub_rn(__fadd_rn(aar[j], ga), inter);
                float iou = __fdiv_rn(inter, denom);      // IEEE rn, matches reference
                if (iou > best[j]) { best[j] = iou; bc[j] = c; }
                unsigned ib = __float_as_uint(iou);
                if (ib >= min_hi) {
                    unsigned long long key =
                        ((unsigned long long)ib << 32) | (unsigned)(~(unsigned)aidx[j]);
                    cascade_insert(&stop[c * 3], key);
                    min_hi = stop_hi[(c * 3 + 2) * 2 + 1];
                }
            }
        }
    }

#pragma unroll
    for (int j = 0; j < APT; j++) {
        if (act[j]) {
            float r = -2.0f;
            if (best[j] < 0.3f) r = -1.0f;
            if (best[j] > 0.5f) r = (float)sgi[bc[j]];
            out[aidx[j]] = r;
        }
    }

    __syncthreads();
    const unsigned* gtop_hi = (const unsigned*)gtop;
    for (int i = tid; i < cnt * 3; i += TPB) {
        unsigned long long v = stop[i];
        if (!v) continue;
        int orig = sgi[i / 3];
        unsigned gm = gtop_hi[(orig * 3 + 2) * 2 + 1];
        if ((unsigned)(v >> 32) >= gm) cascade_insert(&gtop[orig * 3], v);
    }
}

__global__ void k2_claims(const unsigned long long* __restrict__ gtop, int m,
                          int* __restrict__ forced)
{
    int g = blockIdx.x * blockDim.x + threadIdx.x;
    if (g >= m) return;
    unsigned long long s0 = gtop[g * 3 + 0];
    unsigned long long s1 = gtop[g * 3 + 1];
    unsigned long long s2 = gtop[g * 3 + 2];
    float v0 = __uint_as_float((unsigned)(s0 >> 32));
    float v1 = __uint_as_float((unsigned)(s1 >> 32));
    float v2 = __uint_as_float((unsigned)(s2 >> 32));
    int npos = (v0 > 0.5f) + (v1 > 0.5f) + (v2 > 0.5f);
    bool low = npos < 3;
    // k==0 always claims. Empty slot means all-zero row: ref top_k rank0 = anchor 0.
    if (s0) atomicMax(&forced[(int)(~(unsigned)s0)], g);
    else    atomicMax(&forced[0], g);
    if (low) {
        if (s1 && v1 > 0.1f) atomicMax(&forced[(int)(~(unsigned)s1)], g);
        if (s2 && v2 > 0.1f) atomicMax(&forced[(int)(~(unsigned)s2)], g);
    }
}

__global__ void k3_merge(const int* __restrict__ forced, int n, float* __restrict__ out)
{
    int i = blockIdx.x * blockDim.x + threadIdx.x;
    if (i < n) {
        int f = forced[i];
        if (f >= 0) out[i] = (float)f;
    }
}

extern "C" void kernel_launch(void* const* d_in, const int* in_sizes, int n_in,
                              void* d_out, int out_size)
{
    const float4* anc = (const float4*)d_in[0];
    const float4* gts = (const float4*)d_in[1];
    int n = in_sizes[0] / 4;
    int m = in_sizes[1] / 4;
    float* out = (float*)d_out;

    void *ptop = nullptr, *pforced = nullptr, *phist = nullptr;
    cudaGetSymbolAddress(&ptop, g_top3);
    cudaGetSymbolAddress(&pforced, g_forced);
    cudaGetSymbolAddress(&phist, g_hist);

    cudaMemsetAsync(phist, 0, NCELL * sizeof(int));
    cudaMemsetAsync(ptop, 0, (size_t)m * 3 * sizeof(unsigned long long));
    cudaMemsetAsync(pforced, 0xFF, (size_t)n * sizeof(int));   // -1

    int tblocks = (n + TPB - 1) / TPB;
    k_cells<<<tblocks, TPB>>>(anc, n);
    k_scan<<<1, NCELL>>>(n);
    k_gtlist<<<1, NCELL>>>(gts, m);
    k_scatter<<<tblocks, TPB>>>(anc, n);
    int mblocks = NCELL + (n + CHUNK - 1) / CHUNK;
    k_main<<<mblocks, TPB>>>(gts, out, (unsigned long long*)ptop);
    k2_claims<<<1, 256>>>((const unsigned long long*)ptop, m, (int*)pforced);
    k3_merge<<<tblocks, TPB>>>((const int*)pforced, n, out);
}

// round 4
// speedup vs baseline: 3.2444x; 3.2444x over previous
#include <cuda_runtime.h>
#include <cstdint>

// S3FD anchor assignment: spatial binning via atomic-free counting sort.
//   k_hist:     per-anchor cell id (16x16 grid, 64px cells, by center) +
//               per-block smem histogram -> g_blockhist[cell][block]  (NO global atomics)
//   k_cellscan: per-cell exclusive scan of block counts (in place) + cell totals
//   k_offs:     scan cell totals -> bin offsets; build 1024-anchor chunk worklist
//   k_scatter:  smem cursors = offs[c] + blockbase; smem-atomic rank -> direct write
//   k_gtlist:   per-cell GT list (GT intersecting cell expanded by 65px;
//               64 = max anchor half-extent, +1px center-rounding slack)
//   k_main:     per-chunk IoU vs cell's GT list; max/argmax -> stage-1 assign;
//               per-GT top-3 via lock-free atomicMax cascade (smem -> global)
//   k2:         per-GT claims -> atomicMax scatter into forced[]
//   k3:         assign = forced >= 0 ? forced : assign
// Output dtype float32 (small ints as floats). IoU math uses __f*_rn intrinsics:
// bit-identical to the float32 reference. Pruned pairs always have inter==0 and
// cannot affect strict-> argmax (best init 0) or the iou>0-gated top-3.

#define TPB 256
#define APT 4
#define CHUNK (TPB * APT)      // 1024 anchors per work chunk
#define MAXM 256               // >= n_gt (200)
#define MAXN (1 << 20)         // >= n_anchor (500000)
#define NB_MAX (MAXN / TPB)    // max blocks of 256 anchors
#define NCELL 256
#define GRIDW 16
#define CELL_PX 64.0f
#define EXPAND 65.0f

__device__ unsigned char g_cellid[MAXN];
__device__ int g_blockhist[NCELL * NB_MAX];     // cell-major: [cell * nb + block]
__device__ int g_celltotal[NCELL];
__device__ int g_offs[NCELL];
__device__ int g_nwork;
__device__ int4 g_work[NCELL + MAXN / CHUNK + 2];
__device__ int g_binned[MAXN];                  // binned pos -> original anchor idx
__device__ float4 g_bbox[MAXN];                 // binned anchor boxes (coalesced)
__device__ int g_gtcnt[NCELL];
__device__ int g_gtlist[NCELL * MAXM];
__device__ unsigned long long g_top3[MAXM * 3];
__device__ int g_forced[MAXN];

// Lock-free top-3 insert: slots monotone non-decreasing under atomicMax; the
// displaced minimum cascades down. Keys distinct (low bits = ~anchor idx), so
// final state is the exact sorted top-3 of all inserted keys.
__device__ __forceinline__ void cascade_insert(unsigned long long* s, unsigned long long v) {
#pragma unroll
    for (int i = 0; i < 3; i++) {
        unsigned long long old = atomicMax(&s[i], v);
        v = old < v ? old : v;
        if (v == 0ull) return;
    }
}

__device__ __forceinline__ int cell_of(float4 a) {
    int cx = min(GRIDW - 1, max(0, (int)((a.x + a.z) * (0.5f / CELL_PX))));
    int cy = min(GRIDW - 1, max(0, (int)((a.y + a.w) * (0.5f / CELL_PX))));
    return cy * GRIDW + cx;
}

__global__ void __launch_bounds__(TPB) k_hist(const float4* __restrict__ anc, int n) {
    __shared__ int h[NCELL];
    const int t = threadIdx.x, b = blockIdx.x;
    h[t] = 0;
    __syncthreads();
    int i = b * TPB + t;
    if (i < n) {
        int c = cell_of(anc[i]);
        g_cellid[i] = (unsigned char)c;
        atomicAdd(&h[c], 1);
    }
    __syncthreads();
    g_blockhist[t * gridDim.x + b] = h[t];
}

// Block c: exclusive-scan its nb block-counts in place; emit cell total.
__global__ void __launch_bounds__(TPB) k_cellscan(int nb) {
    __shared__ int sums[TPB];
    const int c = blockIdx.x, t = threadIdx.x;
    const int per = (nb + TPB - 1) / TPB;
    int* row = &g_blockhist[c * nb];
    int s = 0;
    for (int k = 0; k < per; k++) {
        int idx = t * per + k;
        if (idx < nb) s += row[idx];
    }
    sums[t] = s;
    __syncthreads();
    for (int d = 1; d < TPB; d <<= 1) {
        int x = (t >= d) ? sums[t - d] : 0; __syncthreads();
        sums[t] += x; __syncthreads();
    }
    int run = sums[t] - s;   // exclusive prefix for this thread's chunk
    for (int k = 0; k < per; k++) {
        int idx = t * per + k;
        if (idx < nb) { int v = row[idx]; row[idx] = run; run += v; }
    }
    if (t == TPB - 1) g_celltotal[c] = sums[t];
}

// One block: scan cell totals -> g_offs; build chunk worklist.
__global__ void __launch_bounds__(NCELL) k_offs() {
    __shared__ int s[NCELL];
    const int t = threadIdx.x;
    int v = g_celltotal[t];
    s[t] = v; __syncthreads();
    for (int d = 1; d < NCELL; d <<= 1) {
        int x = (t >= d) ? s[t - d] : 0; __syncthreads();
        s[t] += x; __syncthreads();
    }
    int excl = s[t] - v;
    g_offs[t] = excl;
    int ch = (v + CHUNK - 1) / CHUNK;
    __syncthreads();
    s[t] = ch; __syncthreads();
    for (int d = 1; d < NCELL; d <<= 1) {
        int x = (t >= d) ? s[t - d] : 0; __syncthreads();
        s[t] += x; __syncthreads();
    }
    int chexcl = s[t] - ch;
    if (t == NCELL - 1) g_nwork = s[t];
    for (int k = 0; k < ch; k++)
        g_work[chexcl + k] = make_int4(t, excl + k * CHUNK, min(CHUNK, v - k * CHUNK), 0);
}

__global__ void __launch_bounds__(NCELL) k_gtlist(const float4* __restrict__ gts, int m) {
    int c = threadIdx.x;
    float cx0 = (c & (GRIDW - 1)) * CELL_PX - EXPAND;
    float cx1 = (c & (GRIDW - 1)) * CELL_PX + CELL_PX + EXPAND;
    float cy0 = (c >> 4) * CELL_PX - EXPAND;
    float cy1 = (c >> 4) * CELL_PX + CELL_PX + EXPAND;
    int cnt = 0;
    for (int g = 0; g < m; g++) {
        float4 G = gts[g];
        if (G.x <= cx1 && G.z >= cx0 && G.y <= cy1 && G.w >= cy0)
            g_gtlist[c * MAXM + cnt++] = g;
    }
    g_gtcnt[c] = cnt;
}

__global__ void __launch_bounds__(TPB) k_scatter(const float4* __restrict__ anc, int n, int nb) {
    __shared__ int cur[NCELL];
    const int t = threadIdx.x, b = blockIdx.x;
    cur[t] = g_offs[t] + g_blockhist[t * nb + b];   // this block's base in cell t
    __syncthreads();
    int i = b * TPB + t;
    if (i < n) {
        float4 a = anc[i];
        int c = g_cellid[i];
        int pos = atomicAdd(&cur[c], 1);            // smem atomic, ~1 conflict avg
        g_bbox[pos] = a;
        g_binned[pos] = i;
    }
}

__global__ void __launch_bounds__(TPB) k_main(
    const float4* __restrict__ gts, float* __restrict__ out,
    unsigned long long* __restrict__ gtop)
{
    __shared__ float4 sgc[MAXM];
    __shared__ float sga[MAXM];
    __shared__ int sgi[MAXM];
    __shared__ unsigned long long stop[MAXM * 3];

    if (blockIdx.x >= g_nwork) return;
    int4 w = g_work[blockIdx.x];
    const int cell = w.x, astart = w.y, alen = w.z;
    const int tid = threadIdx.x;

    const int cnt = g_gtcnt[cell];
    if (tid < cnt) {
        int gi = g_gtlist[cell * MAXM + tid];
        float4 G = gts[gi];
        sgc[tid] = G;
        sga[tid] = __fmul_rn(__fsub_rn(G.z, G.x), __fsub_rn(G.w, G.y));
        sgi[tid] = gi;
    }
    for (int i = tid; i < MAXM * 3; i += TPB) stop[i] = 0ull;
    __syncthreads();

    float ax1[APT], ay1[APT], ax2[APT], ay2[APT], aar[APT], best[APT];
    int bc[APT], aidx[APT];
    bool act[APT];
#pragma unroll
    for (int j = 0; j < APT; j++) {
        int p = tid + j * TPB;
        act[j] = p < alen;
        float4 a = act[j] ? g_bbox[astart + p] : make_float4(0.f, 0.f, 0.f, 0.f);
        aidx[j] = act[j] ? g_binned[astart + p] : 0;
        ax1[j] = a.x; ay1[j] = a.y; ax2[j] = a.z; ay2[j] = a.w;
        aar[j] = __fmul_rn(__fsub_rn(a.z, a.x), __fsub_rn(a.w, a.y));
        best[j] = 0.f;   // all-zero row -> ref argmax 0
        bc[j] = 0;
    }

    // Stale-read skip gate: slot-2 high word is monotone non-decreasing; a racy
    // 32-bit read is always a safe lower bound.
    const unsigned* stop_hi = (const unsigned*)stop;

    for (int c = 0; c < cnt; c++) {
        float4 G = sgc[c];
        float ga = sga[c];
        unsigned min_hi = stop_hi[(c * 3 + 2) * 2 + 1];
#pragma unroll
        for (int j = 0; j < APT; j++) {
            float ltx = fmaxf(ax1[j], G.x), lty = fmaxf(ay1[j], G.y);
            float rbx = fminf(ax2[j], G.z), rby = fminf(ay2[j], G.w);
            float wd = fmaxf(__fsub_rn(rbx, ltx), 0.f);
            float ht = fmaxf(__fsub_rn(rby, lty), 0.f);
            float inter = __fmul_rn(wd, ht);
            if (inter > 0.f && act[j]) {
                float denom = __fsub_rn(__fadd_rn(aar[j], ga), inter);
                float iou = __fdiv_rn(inter, denom);    // IEEE rn, matches reference
                if (iou > best[j]) { best[j] = iou; bc[j] = c; }
                unsigned ib = __float_as_uint(iou);
                if (ib >= min_hi) {
                    unsigned long long key =
                        ((unsigned long long)ib << 32) | (unsigned)(~(unsigned)aidx[j]);
                    cascade_insert(&stop[c * 3], key);
                    min_hi = stop_hi[(c * 3 + 2) * 2 + 1];
                }
            }
        }
    }

#pragma unroll
    for (int j = 0; j < APT; j++) {
        if (act[j]) {
            float r = -2.0f;
            if (best[j] < 0.3f) r = -1.0f;
            if (best[j] > 0.5f) r = (float)sgi[bc[j]];
            out[aidx[j]] = r;
        }
    }

    __syncthreads();
    const unsigned* gtop_hi = (const unsigned*)gtop;
    for (int i = tid; i < cnt * 3; i += TPB) {
        unsigned long long v = stop[i];
        if (!v) continue;
        int orig = sgi[i / 3];
        unsigned gm = gtop_hi[(orig * 3 + 2) * 2 + 1];
        if ((unsigned)(v >> 32) >= gm) cascade_insert(&gtop[orig * 3], v);
    }
}

__global__ void k2_claims(const unsigned long long* __restrict__ gtop, int m,
                          int* __restrict__ forced)
{
    int g = blockIdx.x * blockDim.x + threadIdx.x;
    if (g >= m) return;
    unsigned long long s0 = gtop[g * 3 + 0];
    unsigned long long s1 = gtop[g * 3 + 1];
    unsigned long long s2 = gtop[g * 3 + 2];
    float v0 = __uint_as_float((unsigned)(s0 >> 32));
    float v1 = __uint_as_float((unsigned)(s1 >> 32));
    float v2 = __uint_as_float((unsigned)(s2 >> 32));
    int npos = (v0 > 0.5f) + (v1 > 0.5f) + (v2 > 0.5f);
    bool low = npos < 3;
    // k==0 always claims. Empty slot 0 = all-zero row: ref top_k rank0 -> anchor 0.
    if (s0) atomicMax(&forced[(int)(~(unsigned)s0)], g);
    else    atomicMax(&forced[0], g);
    if (low) {
        if (s1 && v1 > 0.1f) atomicMax(&forced[(int)(~(unsigned)s1)], g);
        if (s2 && v2 > 0.1f) atomicMax(&forced[(int)(~(unsigned)s2)], g);
    }
}

__global__ void k3_merge(const int* __restrict__ forced, int n, float* __restrict__ out)
{
    int i = blockIdx.x * blockDim.x + threadIdx.x;
    if (i < n) {
        int f = forced[i];
        if (f >= 0) out[i] = (float)f;
    }
}

extern "C" void kernel_launch(void* const* d_in, const int* in_sizes, int n_in,
                              void* d_out, int out_size)
{
    const float4* anc = (const float4*)d_in[0];
    const float4* gts = (const float4*)d_in[1];
    int n = in_sizes[0] / 4;
    int m = in_sizes[1] / 4;
    float* out = (float*)d_out;

    void *ptop = nullptr, *pforced = nullptr;
    cudaGetSymbolAddress(&ptop, g_top3);
    cudaGetSymbolAddress(&pforced, g_forced);

    cudaMemsetAsync(ptop, 0, (size_t)m * 3 * sizeof(unsigned long long));
    cudaMemsetAsync(pforced, 0xFF, (size_t)n * sizeof(int));   // -1

    int nb = (n + TPB - 1) / TPB;
    k_hist<<<nb, TPB>>>(anc, n);
    k_cellscan<<<NCELL, TPB>>>(nb);
    k_offs<<<1, NCELL>>>();
    k_gtlist<<<1, NCELL>>>(gts, m);
    k_scatter<<<nb, TPB>>>(anc, n, nb);
    int mblocks = NCELL + (n + CHUNK - 1) / CHUNK;
    k_main<<<mblocks, TPB>>>(gts, out, (unsigned long long*)ptop);
    k2_claims<<<1, 256>>>((const unsigned long long*)ptop, m, (int*)pforced);
    k3_merge<<<nb, TPB>>>((const int*)pforced, n, out);
}